// round 15
// baseline (speedup 1.0000x reference)
#include <cuda_runtime.h>
#include <cuda_fp16.h>
#include <cuda_bf16.h>
#include <math.h>
#include <stdint.h>

#define BB 32
#define NN 1024
#define HH 256

// Scratch (__device__ globals; no allocations allowed)
static __device__ __half        g_WhH[BB * NN * HH];   // 16 MB fp16 Wh
static __device__ __half        g_att[BB * NN * NN];   // 64 MB fp16 dense normalized att
static __device__ float         g_s1[BB * NN];
static __device__ float         g_s2[BB * NN];
static __device__ __nv_bfloat16 g_WT[4][HH * HH];      // WiH, WiL, WcH, WcL, transposed [n][k]
static __device__ __nv_bfloat16 g_AH[BB * NN * HH];    // 16 MB inp bf16 hi
static __device__ __nv_bfloat16 g_AL[BB * NN * HH];    // 16 MB inp bf16 lo

// ---------------------------------------------------------------------------
__device__ __forceinline__ uint32_t smem_u32(const void* p) {
    uint32_t a;
    asm("{ .reg .u64 t; cvta.to.shared.u64 t, %1; cvt.u32.u64 %0, t; }" : "=r"(a) : "l"(p));
    return a;
}

#define LDSM_X4(r0, r1, r2, r3, addr) \
    asm volatile("ldmatrix.sync.aligned.m8n8.x4.shared.b16 {%0,%1,%2,%3}, [%4];" \
                 : "=r"(r0), "=r"(r1), "=r"(r2), "=r"(r3) : "r"(addr))

#define LDSM_X4_T(r0, r1, r2, r3, addr) \
    asm volatile("ldmatrix.sync.aligned.m8n8.x4.trans.shared.b16 {%0,%1,%2,%3}, [%4];" \
                 : "=r"(r0), "=r"(r1), "=r"(r2), "=r"(r3) : "r"(addr))

#define MMA_BF16(d, a, b0r, b1r) \
    asm volatile("mma.sync.aligned.m16n8k16.row.col.f32.bf16.bf16.f32 " \
                 "{%0,%1,%2,%3}, {%4,%5,%6,%7}, {%8,%9}, {%0,%1,%2,%3};" \
                 : "+f"((d)[0]), "+f"((d)[1]), "+f"((d)[2]), "+f"((d)[3]) \
                 : "r"((a)[0]), "r"((a)[1]), "r"((a)[2]), "r"((a)[3]), \
                   "r"(b0r), "r"(b1r))

#define MMA_F16(d, a, b0r, b1r) \
    asm volatile("mma.sync.aligned.m16n8k16.row.col.f32.f16.f16.f32 " \
                 "{%0,%1,%2,%3}, {%4,%5,%6,%7}, {%8,%9}, {%0,%1,%2,%3};" \
                 : "+f"((d)[0]), "+f"((d)[1]), "+f"((d)[2]), "+f"((d)[3]) \
                 : "r"((a)[0]), "r"((a)[1]), "r"((a)[2]), "r"((a)[3]), \
                   "r"(b0r), "r"(b1r))

#define CP16(dst, src) \
    asm volatile("cp.async.cg.shared.global [%0], [%1], 16;" :: "r"(dst), "l"(src))
#define CP_COMMIT() asm volatile("cp.async.commit_group;" ::: "memory")

// ---------------------------------------------------------------------------
// Kernel 0a: split W_i/W_c into transposed bf16 hi/lo: WT[n][k] = W[k][n]
// ---------------------------------------------------------------------------
__global__ __launch_bounds__(256) void wsplit_kernel(
    const float* __restrict__ Wi, const float* __restrict__ Wc)
{
    int idx = blockIdx.x * 256 + threadIdx.x;
    int which = idx >> 16;
    int e = idx & 65535;
    int n = e >> 8, k = e & 255;
    const float* W = which ? Wc : Wi;
    float x = W[k * HH + n];
    __nv_bfloat16 h = __float2bfloat16(x);
    __nv_bfloat16 lo = __float2bfloat16(x - __bfloat162float(h));
    g_WT[which * 2][n * HH + k] = h;
    g_WT[which * 2 + 1][n * HH + k] = lo;
}

// ---------------------------------------------------------------------------
// Kernel 0b: split inp into bf16 hi/lo planes (same layout as inp).
// Each thread handles 4 consecutive elements.
// ---------------------------------------------------------------------------
__global__ __launch_bounds__(256) void asplit_kernel(const float* __restrict__ inp)
{
    size_t base = ((size_t)blockIdx.x * 256 + threadIdx.x) * 4;
    float4 v = *(const float4*)(inp + base);
    float xv[4] = {v.x, v.y, v.z, v.w};
    unsigned short h[4], q[4];
    #pragma unroll
    for (int e = 0; e < 4; ++e) {
        __nv_bfloat16 bh = __float2bfloat16(xv[e]);
        h[e] = __bfloat16_as_ushort(bh);
        q[e] = __bfloat16_as_ushort(__float2bfloat16(xv[e] - __bfloat162float(bh)));
    }
    *(uint2*)(g_AH + base) = make_uint2(h[0] | ((uint32_t)h[1] << 16),
                                        h[2] | ((uint32_t)h[3] << 16));
    *(uint2*)(g_AL + base) = make_uint2(q[0] | ((uint32_t)q[1] << 16),
                                        q[2] | ((uint32_t)q[3] << 16));
}

// ---------------------------------------------------------------------------
// Kernel 1 v4: mma.sync bf16 3-term split GEMM, 128x256 per CTA, 512 threads,
// warp tile 32x64 (r13-proven shape). 3-stage cp.async pipeline, one sync per
// chunk; all operands pre-split in global (no conversion in the hot loop).
// Fragment formulas and epilogue identical to the r13-validated version.
// ---------------------------------------------------------------------------
#define PADK 40
#define ABUF (2 * 128 * PADK * 2)              // 20480 per stage (hi+lo planes)
#define BBUF (2 * 256 * PADK * 2)              // 40960 per stage
#define OFF_A   0                              // stage s at s*ABUF
#define OFF_B   (3 * ABUF)                     // 61440; stage s at +s*BBUF
#define OFF_AV  (OFF_B + 3 * BBUF)             // 184320
#define OFF_RED (OFF_AV + 512 * 4)             // 186368
#define SMEM_TOT (OFF_RED + 4 * 128 * 2 * 4)   // 190464

__global__ __launch_bounds__(512) void gemm_kernel(const int* __restrict__ l,
                                                   const float* __restrict__ avec)
{
    extern __shared__ char smem[];
    const uint32_t sbA = smem_u32(smem) + OFF_A;
    const uint32_t sbB = smem_u32(smem) + OFF_B;
    float* sAv  = (float*)(smem + OFF_AV);
    float* sRed = (float*)(smem + OFF_RED);

    const int tid = threadIdx.x, lane = tid & 31, wid = tid >> 5;
    const int warpRow = wid >> 2, warpCol = wid & 3;
    const int rowTile = blockIdx.x * 128;
    const int b = rowTile >> 10;
    const int n0 = rowTile & 1023;
    const int l0 = l[2 * b], l1 = l[2 * b + 1];
    const bool mixed = (l0 > n0 && l0 < n0 + 128) || (l1 > n0 && l1 < n0 + 128);
    const bool sel0  = (n0 >= l0 && n0 < l1);
    const int npass  = mixed ? 2 : 1;

    sAv[tid] = avec[tid];

    for (int pass = 0; pass < npass; ++pass) {
        const bool useWi = mixed ? (pass == 0) : sel0;
        const __nv_bfloat16* __restrict__ Bh = g_WT[useWi ? 0 : 2];
        const __nv_bfloat16* __restrict__ Bl = g_WT[useWi ? 1 : 3];
        const __nv_bfloat16* __restrict__ Ah = g_AH + (size_t)rowTile * HH;
        const __nv_bfloat16* __restrict__ Al = g_AL + (size_t)rowTile * HH;

        float acc[2][8][4];
        #pragma unroll
        for (int mt = 0; mt < 2; ++mt)
            #pragma unroll
            for (int nt = 0; nt < 8; ++nt)
                #pragma unroll
                for (int e = 0; e < 4; ++e) acc[mt][nt][e] = 0.0f;

        // per-stage cp.async: A planes 2x(128x32) = 1024 segs; B 2x(256x32) = 2048 segs
        auto load_stage = [&](int kc, int s) {
            const int k0 = kc * 32;
            uint32_t aS = sbA + (uint32_t)s * ABUF;
            uint32_t bS = sbB + (uint32_t)s * BBUF;
            {
                int r = tid >> 2, c = (tid & 3) * 8;         // 128 rows x 4 segs
                CP16(aS + (uint32_t)(r * PADK + c) * 2, Ah + (size_t)r * HH + k0 + c);
                CP16(aS + (uint32_t)((128 + r) * PADK + c) * 2, Al + (size_t)r * HH + k0 + c);
            }
            #pragma unroll
            for (int it = 0; it < 2; ++it) {
                int f = tid + it * 512;                      // 0..1023: 256 rows x 4 segs
                int r = f >> 2, c = (f & 3) * 8;
                CP16(bS + (uint32_t)(r * PADK + c) * 2, Bh + (size_t)r * HH + k0 + c);
                CP16(bS + (uint32_t)((256 + r) * PADK + c) * 2, Bl + (size_t)r * HH + k0 + c);
            }
            CP_COMMIT();
        };

        load_stage(0, 0);
        load_stage(1, 1);

        int sIdx = 0;
        for (int kc = 0; kc < 8; ++kc) {
            if (kc == 7) {
                asm volatile("cp.async.wait_group 0;" ::: "memory");
            } else {
                asm volatile("cp.async.wait_group 1;" ::: "memory");
            }
            __syncthreads();   // chunk kc ready; all done consuming kc-1

            if (kc + 2 < 8) {
                int s2 = sIdx + 2; if (s2 >= 3) s2 -= 3;
                load_stage(kc + 2, s2);
            }

            const uint32_t aS = sbA + (uint32_t)sIdx * ABUF;
            const uint32_t bS = sbB + (uint32_t)sIdx * BBUF;
            #pragma unroll
            for (int ks = 0; ks < 2; ++ks) {
                const int kk = ks * 16;
                uint32_t ah[2][4], al[2][4];
                #pragma unroll
                for (int mt = 0; mt < 2; ++mt) {
                    int row = warpRow * 32 + mt * 16 + (lane & 15);
                    int kcol = kk + (lane >> 4) * 8;
                    uint32_t ad = aS + (uint32_t)(row * PADK + kcol) * 2;
                    LDSM_X4(ah[mt][0], ah[mt][1], ah[mt][2], ah[mt][3], ad);
                    LDSM_X4(al[mt][0], al[mt][1], al[mt][2], al[mt][3],
                            ad + 128 * PADK * 2);
                }
                #pragma unroll
                for (int p = 0; p < 4; ++p) {
                    int row = warpCol * 64 + p * 16 + (lane & 7) + ((lane >> 4) << 3);
                    int kcol = kk + (((lane >> 3) & 1) << 3);
                    uint32_t bd = bS + (uint32_t)(row * PADK + kcol) * 2;
                    uint32_t bh[4], bl[4];
                    LDSM_X4(bh[0], bh[1], bh[2], bh[3], bd);
                    LDSM_X4(bl[0], bl[1], bl[2], bl[3], bd + 256 * PADK * 2);
                    #pragma unroll
                    for (int mt = 0; mt < 2; ++mt) {
                        MMA_BF16(acc[mt][2 * p],     ah[mt], bh[0], bh[1]);
                        MMA_BF16(acc[mt][2 * p],     al[mt], bh[0], bh[1]);
                        MMA_BF16(acc[mt][2 * p],     ah[mt], bl[0], bl[1]);
                        MMA_BF16(acc[mt][2 * p + 1], ah[mt], bh[2], bh[3]);
                        MMA_BF16(acc[mt][2 * p + 1], al[mt], bh[2], bh[3]);
                        MMA_BF16(acc[mt][2 * p + 1], ah[mt], bl[2], bl[3]);
                    }
                }
            }
            ++sIdx; if (sIdx == 3) sIdx = 0;
        }

        // ---- epilogue: fp16 Wh store + fused s1/s2 dots (r13-identical) ----
        __syncthreads();
        const int g = lane >> 2, qc = (lane & 3) * 2;
        #pragma unroll
        for (int mt = 0; mt < 2; ++mt) {
            int lr0 = warpRow * 32 + mt * 16 + g;
            int lr1 = lr0 + 8;
            int gr0 = rowTile + lr0, gr1 = rowTile + lr1;   // global (addressing)
            int nr0 = n0 + lr0, nr1 = n0 + lr1;             // within-batch (masking)
            bool dw0 = !mixed || (((nr0 >= l0) && (nr0 < l1)) == useWi);
            bool dw1 = !mixed || (((nr1 >= l0) && (nr1 < l1)) == useWi);
            float s1r0 = 0, s2r0 = 0, s1r1 = 0, s2r1 = 0;
            #pragma unroll
            for (int nt = 0; nt < 8; ++nt) {
                int col = warpCol * 64 + nt * 8 + qc;
                float a0 = sAv[col], a1 = sAv[col + 1];
                float b0 = sAv[256 + col], b1 = sAv[256 + col + 1];
                float c0 = acc[mt][nt][0], c1 = acc[mt][nt][1];
                float c2 = acc[mt][nt][2], c3 = acc[mt][nt][3];
                s1r0 = fmaf(c0, a0, fmaf(c1, a1, s1r0));
                s2r0 = fmaf(c0, b0, fmaf(c1, b1, s2r0));
                s1r1 = fmaf(c2, a0, fmaf(c3, a1, s1r1));
                s2r1 = fmaf(c2, b0, fmaf(c3, b1, s2r1));
                if (dw0)
                    *(__half2*)(g_WhH + (size_t)gr0 * HH + col) = __floats2half2_rn(c0, c1);
                if (dw1)
                    *(__half2*)(g_WhH + (size_t)gr1 * HH + col) = __floats2half2_rn(c2, c3);
            }
            #pragma unroll
            for (int d = 1; d <= 2; d <<= 1) {
                s1r0 += __shfl_xor_sync(0xffffffffu, s1r0, d);
                s2r0 += __shfl_xor_sync(0xffffffffu, s2r0, d);
                s1r1 += __shfl_xor_sync(0xffffffffu, s1r1, d);
                s2r1 += __shfl_xor_sync(0xffffffffu, s2r1, d);
            }
            if ((lane & 3) == 0) {
                sRed[(warpCol * 128 + lr0) * 2 + 0] = s1r0;
                sRed[(warpCol * 128 + lr0) * 2 + 1] = s2r0;
                sRed[(warpCol * 128 + lr1) * 2 + 0] = s1r1;
                sRed[(warpCol * 128 + lr1) * 2 + 1] = s2r1;
            }
        }
        __syncthreads();
        if (tid < 128) {
            int grow = rowTile + tid;
            int nrow = n0 + tid;
            bool dw = !mixed || (((nrow >= l0) && (nrow < l1)) == useWi);
            if (dw) {
                float v1 = 0, v2 = 0;
                #pragma unroll
                for (int wc = 0; wc < 4; ++wc) {
                    v1 += sRed[(wc * 128 + tid) * 2 + 0];
                    v2 += sRed[(wc * 128 + tid) * 2 + 1];
                }
                g_s1[grow] = v1;
                g_s2[grow] = v2;
            }
        }
        __syncthreads();
    }
}

// ---------------------------------------------------------------------------
// Kernel 2 (r11-validated, unchanged): masked softmax -> dense fp16 att row.
// ---------------------------------------------------------------------------
__global__ __launch_bounds__(128) void score_kernel(
    const float* __restrict__ A, __half* __restrict__ att)
{
    __shared__ float s_red[8];

    const int bi = blockIdx.x;
    const int b = bi >> 10, i = bi & 1023;
    const int tid = threadIdx.x, lane = tid & 31, w = tid >> 5;
    const float* Arow = A + (size_t)bi * NN;
    const float* s2b = g_s2 + (size_t)b * NN;
    const float s1i = g_s1[bi];

    float av[8];
    {
        float4 v0 = *(const float4*)(Arow + tid * 8);
        float4 v1 = *(const float4*)(Arow + tid * 8 + 4);
        av[0] = v0.x; av[1] = v0.y; av[2] = v0.z; av[3] = v0.w;
        av[4] = v1.x; av[5] = v1.y; av[6] = v1.z; av[7] = v1.w;
    }
    unsigned pbits = 0;
    float xv[8];
    float lmax = -INFINITY;
    #pragma unroll
    for (int q = 0; q < 8; ++q) {
        int j = tid * 8 + q;
        float aval = av[q] + ((j == i) ? 1.0f : 0.0f);   // A + I (diag may be 2)
        if (aval > 0.0f) {
            float x = (s1i + s2b[j]) * aval;
            x = (x > 0.0f) ? x : 0.2f * x;               // leaky relu
            xv[q] = x;
            pbits |= (1u << q);
            lmax = fmaxf(lmax, x);
        }
    }
    float wm = lmax;
    #pragma unroll
    for (int d = 16; d > 0; d >>= 1) wm = fmaxf(wm, __shfl_xor_sync(0xffffffffu, wm, d));
    if (lane == 0) s_red[w] = wm;
    __syncthreads();
    const float m = fmaxf(fmaxf(s_red[0], s_red[1]), fmaxf(s_red[2], s_red[3]));

    float wv[8];
    float lz = 0.0f;
    #pragma unroll
    for (int q = 0; q < 8; ++q) {
        float e = (pbits & (1u << q)) ? __expf(xv[q] - m) : 0.0f;
        wv[q] = e;
        lz += e;
    }
    #pragma unroll
    for (int d = 16; d > 0; d >>= 1) lz += __shfl_xor_sync(0xffffffffu, lz, d);
    if (lane == 0) s_red[4 + w] = lz;
    __syncthreads();
    const float Zi = 1.0f / (s_red[4] + s_red[5] + s_red[6] + s_red[7]);

    __half2 hv[4];
    #pragma unroll
    for (int q = 0; q < 4; ++q)
        hv[q] = __floats2half2_rn(wv[2 * q] * Zi, wv[2 * q + 1] * Zi);
    *(int4*)(att + (size_t)bi * NN + tid * 8) = *(const int4*)hv;
}

// ---------------------------------------------------------------------------
// Kernel 3 (r13-validated, unchanged): out = elu(att @ Wh). 128x256 tile per
// CTA, 512 threads, warp tile 32x64, 3-stage cp.async, one sync per chunk.
// ---------------------------------------------------------------------------
#define BPADK 72
#define V4_A_STAGE (128 * BPADK * 2)            // 18432
#define V4_B_STAGE (64 * 264 * 2)               // 33792
#define V4_OFF_B   (3 * V4_A_STAGE)             // 55296
#define V4_SMEM    (V4_OFF_B + 3 * V4_B_STAGE)  // 156672

__global__ __launch_bounds__(512) void bmm_kernel(
    const __half* __restrict__ att, const __half* __restrict__ Wh,
    float* __restrict__ out)
{
    extern __shared__ char bsm[];
    const uint32_t aBase = smem_u32(bsm);
    const uint32_t bBase = aBase + V4_OFF_B;

    const int tid = threadIdx.x, lane = tid & 31, wid = tid >> 5;
    const int warpRow = wid >> 2, warpCol = wid & 3;
    const int b  = blockIdx.x >> 3;
    const int rt = (blockIdx.x & 7) * 128;
    const __half* attB = att + ((size_t)b * NN + rt) * NN;
    const __half* WhB  = Wh + (size_t)b * NN * HH;

    float acc[2][8][4];
    #pragma unroll
    for (int mt = 0; mt < 2; ++mt)
        #pragma unroll
        for (int nt = 0; nt < 8; ++nt)
            #pragma unroll
            for (int e = 0; e < 4; ++e) acc[mt][nt][e] = 0.0f;

    auto load_stage = [&](int kc, int s) {
        const int k0 = kc * 64;
        uint32_t aS = aBase + (uint32_t)s * V4_A_STAGE;
        uint32_t bS = bBase + (uint32_t)s * V4_B_STAGE;
        #pragma unroll
        for (int it = 0; it < 2; ++it) {
            int f = tid + it * 512;                 // 0..1023: 128 rows x 8 segs
            int r = f >> 3, c = (f & 7) * 8;
            CP16(aS + (uint32_t)(r * BPADK + c) * 2,
                 attB + (size_t)r * NN + k0 + c);
        }
        #pragma unroll
        for (int it = 0; it < 4; ++it) {
            int f = tid + it * 512;                 // 0..2047: 64 rows x 32 segs
            int r = f >> 5, c = (f & 31) * 8;
            CP16(bS + (uint32_t)(r * 264 + c) * 2,
                 WhB + (size_t)(k0 + r) * HH + c);
        }
        CP_COMMIT();
    };

    load_stage(0, 0);
    load_stage(1, 1);

    int sIdx = 0;
    for (int kc = 0; kc < 16; ++kc) {
        if (kc == 15) {
            asm volatile("cp.async.wait_group 0;" ::: "memory");
        } else {
            asm volatile("cp.async.wait_group 1;" ::: "memory");
        }
        __syncthreads();   // chunk kc ready; everyone done consuming kc-1

        if (kc + 2 < 16) {
            int s2 = sIdx + 2; if (s2 >= 3) s2 -= 3;
            load_stage(kc + 2, s2);
        }

        const uint32_t aS = aBase + (uint32_t)sIdx * V4_A_STAGE;
        const uint32_t bS = bBase + (uint32_t)sIdx * V4_B_STAGE;
        #pragma unroll
        for (int ks = 0; ks < 4; ++ks) {
            const int kk = ks * 16;
            uint32_t a[2][4];
            #pragma unroll
            for (int mt = 0; mt < 2; ++mt) {
                int row = warpRow * 32 + mt * 16 + (lane & 15);
                int kcol = kk + (lane >> 4) * 8;
                LDSM_X4(a[mt][0], a[mt][1], a[mt][2], a[mt][3],
                        aS + (uint32_t)(row * BPADK + kcol) * 2);
            }
            #pragma unroll
            for (int p = 0; p < 4; ++p) {
                int n = warpCol * 64 + p * 16;
                int krow = kk + (lane & 15);
                int col = n + ((lane >> 4) << 3);
                uint32_t bfr[4];
                LDSM_X4_T(bfr[0], bfr[1], bfr[2], bfr[3],
                          bS + (uint32_t)(krow * 264 + col) * 2);
                #pragma unroll
                for (int mt = 0; mt < 2; ++mt) {
                    MMA_F16(acc[mt][2 * p],     a[mt], bfr[0], bfr[1]);
                    MMA_F16(acc[mt][2 * p + 1], a[mt], bfr[2], bfr[3]);
                }
            }
        }

        ++sIdx; if (sIdx == 3) sIdx = 0;
    }

    // ---- epilogue: elu + fp32 store ----
    const int g = lane >> 2, qc = (lane & 3) * 2;
    #pragma unroll
    for (int mt = 0; mt < 2; ++mt) {
        int lr0 = warpRow * 32 + mt * 16 + g;
        int lr1 = lr0 + 8;
        size_t o0 = ((size_t)b * NN + rt + lr0) * HH;
        size_t o1 = ((size_t)b * NN + rt + lr1) * HH;
        #pragma unroll
        for (int nt = 0; nt < 8; ++nt) {
            int col = warpCol * 64 + nt * 8 + qc;
            float c0 = acc[mt][nt][0], c1 = acc[mt][nt][1];
            float c2 = acc[mt][nt][2], c3 = acc[mt][nt][3];
            float2 r0, r1;
            r0.x = (c0 > 0.0f) ? c0 : expm1f(c0);
            r0.y = (c1 > 0.0f) ? c1 : expm1f(c1);
            r1.x = (c2 > 0.0f) ? c2 : expm1f(c2);
            r1.y = (c3 > 0.0f) ? c3 : expm1f(c3);
            *(float2*)(out + o0 + col) = r0;
            *(float2*)(out + o1 + col) = r1;
        }
    }
}

// ---------------------------------------------------------------------------
extern "C" void kernel_launch(void* const* d_in, const int* in_sizes, int n_in,
                              void* d_out, int out_size)
{
    const float* inp = (const float*)d_in[0];   // [B,N,H]
    const float* A   = (const float*)d_in[1];   // [B,N,N]
    const int*   l   = (const int*)  d_in[2];   // [B,2]
    const float* Wi  = (const float*)d_in[3];   // [H,H]
    const float* Wc  = (const float*)d_in[4];   // [H,H]
    const float* a   = (const float*)d_in[5];   // [2H,1]
    float* out = (float*)d_out;

    __half *WhH, *att;
    cudaGetSymbolAddress((void**)&WhH, g_WhH);
    cudaGetSymbolAddress((void**)&att, g_att);

    cudaFuncSetAttribute(gemm_kernel, cudaFuncAttributeMaxDynamicSharedMemorySize, SMEM_TOT);
    cudaFuncSetAttribute(bmm_kernel, cudaFuncAttributeMaxDynamicSharedMemorySize, V4_SMEM);

    wsplit_kernel<<<2 * HH * HH / 256, 256>>>(Wi, Wc);
    asplit_kernel<<<BB * NN * HH / (256 * 4), 256>>>(inp);
    gemm_kernel<<<BB * NN / 128, 512, SMEM_TOT>>>(l, a);
    score_kernel<<<BB * NN, 128>>>(A, att);
    bmm_kernel<<<BB * NN / 128, 512, V4_SMEM>>>(att, WhH, out);
}

// round 17
// speedup vs baseline: 1.1555x; 1.1555x over previous
#include <cuda_runtime.h>
#include <cuda_fp16.h>
#include <cuda_bf16.h>
#include <math.h>
#include <stdint.h>

#define BB 32
#define NN 1024
#define HH 256

// Scratch (__device__ globals; no allocations allowed)
static __device__ __half        g_WhH[BB * NN * HH];   // 16 MB fp16 Wh
static __device__ __half        g_att[BB * NN * NN];   // 64 MB fp16 dense normalized att
static __device__ float         g_s1[BB * NN];
static __device__ float         g_s2[BB * NN];
static __device__ __nv_bfloat16 g_WT[4][HH * HH];      // WiH, WiL, WcH, WcL, transposed [n][k]

// ---------------------------------------------------------------------------
__device__ __forceinline__ uint32_t smem_u32(const void* p) {
    uint32_t a;
    asm("{ .reg .u64 t; cvta.to.shared.u64 t, %1; cvt.u32.u64 %0, t; }" : "=r"(a) : "l"(p));
    return a;
}

#define LDSM_X4(r0, r1, r2, r3, addr) \
    asm volatile("ldmatrix.sync.aligned.m8n8.x4.shared.b16 {%0,%1,%2,%3}, [%4];" \
                 : "=r"(r0), "=r"(r1), "=r"(r2), "=r"(r3) : "r"(addr))

#define LDSM_X4_T(r0, r1, r2, r3, addr) \
    asm volatile("ldmatrix.sync.aligned.m8n8.x4.trans.shared.b16 {%0,%1,%2,%3}, [%4];" \
                 : "=r"(r0), "=r"(r1), "=r"(r2), "=r"(r3) : "r"(addr))

#define MMA_BF16(d, a, b0r, b1r) \
    asm volatile("mma.sync.aligned.m16n8k16.row.col.f32.bf16.bf16.f32 " \
                 "{%0,%1,%2,%3}, {%4,%5,%6,%7}, {%8,%9}, {%0,%1,%2,%3};" \
                 : "+f"((d)[0]), "+f"((d)[1]), "+f"((d)[2]), "+f"((d)[3]) \
                 : "r"((a)[0]), "r"((a)[1]), "r"((a)[2]), "r"((a)[3]), \
                   "r"(b0r), "r"(b1r))

#define MMA_F16(d, a, b0r, b1r) \
    asm volatile("mma.sync.aligned.m16n8k16.row.col.f32.f16.f16.f32 " \
                 "{%0,%1,%2,%3}, {%4,%5,%6,%7}, {%8,%9}, {%0,%1,%2,%3};" \
                 : "+f"((d)[0]), "+f"((d)[1]), "+f"((d)[2]), "+f"((d)[3]) \
                 : "r"((a)[0]), "r"((a)[1]), "r"((a)[2]), "r"((a)[3]), \
                   "r"(b0r), "r"(b1r))

#define CP16(dst, src) \
    asm volatile("cp.async.cg.shared.global [%0], [%1], 16;" :: "r"(dst), "l"(src))
#define CP_COMMIT() asm volatile("cp.async.commit_group;" ::: "memory")

// ---------------------------------------------------------------------------
// Kernel 0: split W_i/W_c into transposed bf16 hi/lo: WT[n][k] = W[k][n]
// ---------------------------------------------------------------------------
__global__ __launch_bounds__(256) void wsplit_kernel(
    const float* __restrict__ Wi, const float* __restrict__ Wc)
{
    int idx = blockIdx.x * 256 + threadIdx.x;
    int which = idx >> 16;
    int e = idx & 65535;
    int n = e >> 8, k = e & 255;
    const float* W = which ? Wc : Wi;
    float x = W[k * HH + n];
    __nv_bfloat16 h = __float2bfloat16(x);
    __nv_bfloat16 lo = __float2bfloat16(x - __bfloat162float(h));
    g_WT[which * 2][n * HH + k] = h;
    g_WT[which * 2 + 1][n * HH + k] = lo;
}

// ---------------------------------------------------------------------------
// Kernel 1 (r13-validated, unchanged): mma.sync bf16 3-term split GEMM,
// 128x256 per CTA, 512 threads, double-buffered smem + register prefetch.
// Fused s1/s2 dots + fp16 Wh store.
// ---------------------------------------------------------------------------
#define PADK 40
#define ABUF (2 * 128 * PADK * 2)
#define BBUF (2 * 256 * PADK * 2)
#define OFF_A   0
#define OFF_B   (2 * ABUF)
#define OFF_AV  (OFF_B + 2 * BBUF)
#define OFF_RED (OFF_AV + 512 * 4)
#define SMEM_TOT (OFF_RED + 4 * 128 * 2 * 4)

__global__ __launch_bounds__(512) void gemm_kernel(
    const float* __restrict__ inp, const int* __restrict__ l,
    const float* __restrict__ avec)
{
    extern __shared__ char smem[];
    const uint32_t sbA = smem_u32(smem) + OFF_A;
    const uint32_t sbB = smem_u32(smem) + OFF_B;
    float* sAv  = (float*)(smem + OFF_AV);
    float* sRed = (float*)(smem + OFF_RED);

    const int tid = threadIdx.x, lane = tid & 31, wid = tid >> 5;
    const int warpRow = wid >> 2, warpCol = wid & 3;
    const int rowTile = blockIdx.x * 128;
    const int b = rowTile >> 10;
    const int n0 = rowTile & 1023;
    const int l0 = l[2 * b], l1 = l[2 * b + 1];
    const bool mixed = (l0 > n0 && l0 < n0 + 128) || (l1 > n0 && l1 < n0 + 128);
    const bool sel0  = (n0 >= l0 && n0 < l1);
    const int npass  = mixed ? 2 : 1;

    sAv[tid] = avec[tid];

    for (int pass = 0; pass < npass; ++pass) {
        const bool useWi = mixed ? (pass == 0) : sel0;
        const __nv_bfloat16* __restrict__ Bh = g_WT[useWi ? 0 : 2];
        const __nv_bfloat16* __restrict__ Bl = g_WT[useWi ? 1 : 3];

        float acc[2][8][4];
        #pragma unroll
        for (int mt = 0; mt < 2; ++mt)
            #pragma unroll
            for (int nt = 0; nt < 8; ++nt)
                #pragma unroll
                for (int e = 0; e < 4; ++e) acc[mt][nt][e] = 0.0f;

        float4 aReg[2];
        int4   bhReg[2], blReg[2];

        auto load_regs = [&](int kc) {
            const int k0 = kc * 32;
            #pragma unroll
            for (int it = 0; it < 2; ++it) {
                int f = tid + it * 512;
                int r = f >> 3, c4 = (f & 7) * 4;
                aReg[it] = *(const float4*)(inp + (size_t)(rowTile + r) * HH + k0 + c4);
            }
            #pragma unroll
            for (int it = 0; it < 2; ++it) {
                int gI = tid + it * 512;
                int r = gI >> 2, c8 = (gI & 3) * 8;
                bhReg[it] = *(const int4*)(Bh + (size_t)r * HH + k0 + c8);
                blReg[it] = *(const int4*)(Bl + (size_t)r * HH + k0 + c8);
            }
        };

        load_regs(0);

        for (int kc = 0; kc < 8; ++kc) {
            const int s = kc & 1;
            const uint32_t aS = sbA + (uint32_t)s * ABUF;
            const uint32_t bS = sbB + (uint32_t)s * BBUF;

            #pragma unroll
            for (int it = 0; it < 2; ++it) {
                int f = tid + it * 512;
                int r = f >> 3, c4 = (f & 7) * 4;
                float xv[4] = {aReg[it].x, aReg[it].y, aReg[it].z, aReg[it].w};
                unsigned short h[4], q[4];
                #pragma unroll
                for (int e = 0; e < 4; ++e) {
                    __nv_bfloat16 bh = __float2bfloat16(xv[e]);
                    h[e] = __bfloat16_as_ushort(bh);
                    q[e] = __bfloat16_as_ushort(
                        __float2bfloat16(xv[e] - __bfloat162float(bh)));
                }
                uint2 hv = make_uint2(h[0] | ((uint32_t)h[1] << 16),
                                      h[2] | ((uint32_t)h[3] << 16));
                uint2 lv = make_uint2(q[0] | ((uint32_t)q[1] << 16),
                                      q[2] | ((uint32_t)q[3] << 16));
                *(uint2*)(smem + OFF_A + s * ABUF + ((size_t)r * PADK + c4) * 2) = hv;
                *(uint2*)(smem + OFF_A + s * ABUF + ((size_t)(128 + r) * PADK + c4) * 2) = lv;
            }
            #pragma unroll
            for (int it = 0; it < 2; ++it) {
                int gI = tid + it * 512;
                int r = gI >> 2, c8 = (gI & 3) * 8;
                *(int4*)(smem + OFF_B + s * BBUF + ((size_t)r * PADK + c8) * 2) = bhReg[it];
                *(int4*)(smem + OFF_B + s * BBUF + ((size_t)(256 + r) * PADK + c8) * 2) = blReg[it];
            }
            __syncthreads();

            if (kc < 7) load_regs(kc + 1);

            #pragma unroll
            for (int ks = 0; ks < 2; ++ks) {
                const int kk = ks * 16;
                uint32_t ah[2][4], al[2][4];
                #pragma unroll
                for (int mt = 0; mt < 2; ++mt) {
                    int row = warpRow * 32 + mt * 16 + (lane & 15);
                    int kcol = kk + (lane >> 4) * 8;
                    uint32_t ad = aS + (uint32_t)(row * PADK + kcol) * 2;
                    LDSM_X4(ah[mt][0], ah[mt][1], ah[mt][2], ah[mt][3], ad);
                    LDSM_X4(al[mt][0], al[mt][1], al[mt][2], al[mt][3],
                            ad + 128 * PADK * 2);
                }
                #pragma unroll
                for (int p = 0; p < 4; ++p) {
                    int row = warpCol * 64 + p * 16 + (lane & 7) + ((lane >> 4) << 3);
                    int kcol = kk + (((lane >> 3) & 1) << 3);
                    uint32_t bd = bS + (uint32_t)(row * PADK + kcol) * 2;
                    uint32_t bh[4], bl[4];
                    LDSM_X4(bh[0], bh[1], bh[2], bh[3], bd);
                    LDSM_X4(bl[0], bl[1], bl[2], bl[3], bd + 256 * PADK * 2);
                    #pragma unroll
                    for (int mt = 0; mt < 2; ++mt) {
                        MMA_BF16(acc[mt][2 * p],     ah[mt], bh[0], bh[1]);
                        MMA_BF16(acc[mt][2 * p],     al[mt], bh[0], bh[1]);
                        MMA_BF16(acc[mt][2 * p],     ah[mt], bl[0], bl[1]);
                        MMA_BF16(acc[mt][2 * p + 1], ah[mt], bh[2], bh[3]);
                        MMA_BF16(acc[mt][2 * p + 1], al[mt], bh[2], bh[3]);
                        MMA_BF16(acc[mt][2 * p + 1], ah[mt], bl[2], bl[3]);
                    }
                }
            }
        }

        __syncthreads();
        const int g = lane >> 2, qc = (lane & 3) * 2;
        #pragma unroll
        for (int mt = 0; mt < 2; ++mt) {
            int lr0 = warpRow * 32 + mt * 16 + g;
            int lr1 = lr0 + 8;
            int gr0 = rowTile + lr0, gr1 = rowTile + lr1;   // global (addressing)
            int nr0 = n0 + lr0, nr1 = n0 + lr1;             // within-batch (masking)
            bool dw0 = !mixed || (((nr0 >= l0) && (nr0 < l1)) == useWi);
            bool dw1 = !mixed || (((nr1 >= l0) && (nr1 < l1)) == useWi);
            float s1r0 = 0, s2r0 = 0, s1r1 = 0, s2r1 = 0;
            #pragma unroll
            for (int nt = 0; nt < 8; ++nt) {
                int col = warpCol * 64 + nt * 8 + qc;
                float a0 = sAv[col], a1 = sAv[col + 1];
                float b0 = sAv[256 + col], b1 = sAv[256 + col + 1];
                float c0 = acc[mt][nt][0], c1 = acc[mt][nt][1];
                float c2 = acc[mt][nt][2], c3 = acc[mt][nt][3];
                s1r0 = fmaf(c0, a0, fmaf(c1, a1, s1r0));
                s2r0 = fmaf(c0, b0, fmaf(c1, b1, s2r0));
                s1r1 = fmaf(c2, a0, fmaf(c3, a1, s1r1));
                s2r1 = fmaf(c2, b0, fmaf(c3, b1, s2r1));
                if (dw0)
                    *(__half2*)(g_WhH + (size_t)gr0 * HH + col) = __floats2half2_rn(c0, c1);
                if (dw1)
                    *(__half2*)(g_WhH + (size_t)gr1 * HH + col) = __floats2half2_rn(c2, c3);
            }
            #pragma unroll
            for (int d = 1; d <= 2; d <<= 1) {
                s1r0 += __shfl_xor_sync(0xffffffffu, s1r0, d);
                s2r0 += __shfl_xor_sync(0xffffffffu, s2r0, d);
                s1r1 += __shfl_xor_sync(0xffffffffu, s1r1, d);
                s2r1 += __shfl_xor_sync(0xffffffffu, s2r1, d);
            }
            if ((lane & 3) == 0) {
                sRed[(warpCol * 128 + lr0) * 2 + 0] = s1r0;
                sRed[(warpCol * 128 + lr0) * 2 + 1] = s2r0;
                sRed[(warpCol * 128 + lr1) * 2 + 0] = s1r1;
                sRed[(warpCol * 128 + lr1) * 2 + 1] = s2r1;
            }
        }
        __syncthreads();
        if (tid < 128) {
            int grow = rowTile + tid;
            int nrow = n0 + tid;
            bool dw = !mixed || (((nrow >= l0) && (nrow < l1)) == useWi);
            if (dw) {
                float v1 = 0, v2 = 0;
                #pragma unroll
                for (int wc = 0; wc < 4; ++wc) {
                    v1 += sRed[(wc * 128 + tid) * 2 + 0];
                    v2 += sRed[(wc * 128 + tid) * 2 + 1];
                }
                g_s1[grow] = v1;
                g_s2[grow] = v2;
            }
        }
        __syncthreads();
    }
}

// ---------------------------------------------------------------------------
// Kernel 2 v3: branchless dense masked softmax -> fp16 normalized att row.
// leaky(t) = fmaxf(t, 0.2t); masked lanes get -1e30 sentinel; exp underflows
// to exact 0 for masked entries. No divergent branches, no mask registers.
// ---------------------------------------------------------------------------
__global__ __launch_bounds__(128) void score_kernel(
    const float* __restrict__ A, __half* __restrict__ att)
{
    __shared__ float s_red[8];

    const int bi = blockIdx.x;
    const int b = bi >> 10, i = bi & 1023;
    const int tid = threadIdx.x, lane = tid & 31, w = tid >> 5;
    const float* Arow = A + (size_t)bi * NN;
    const float* s2b = g_s2 + (size_t)b * NN;
    const float s1i = g_s1[bi];

    float av[8], sv[8];
    {
        float4 v0 = *(const float4*)(Arow + tid * 8);
        float4 v1 = *(const float4*)(Arow + tid * 8 + 4);
        av[0] = v0.x; av[1] = v0.y; av[2] = v0.z; av[3] = v0.w;
        av[4] = v1.x; av[5] = v1.y; av[6] = v1.z; av[7] = v1.w;
        float4 u0 = *(const float4*)(s2b + tid * 8);
        float4 u1 = *(const float4*)(s2b + tid * 8 + 4);
        sv[0] = u0.x; sv[1] = u0.y; sv[2] = u0.z; sv[3] = u0.w;
        sv[4] = u1.x; sv[5] = u1.y; sv[6] = u1.z; sv[7] = u1.w;
    }
    if ((i >> 3) == tid) av[i & 7] += 1.0f;    // diagonal of A + I

    float xs[8];
    float lmax = -INFINITY;
    #pragma unroll
    for (int q = 0; q < 8; ++q) {
        float t = (s1i + sv[q]) * av[q];
        float x = fmaxf(t, 0.2f * t);           // leaky relu, branchless
        x = (av[q] > 0.0f) ? x : -1e30f;        // sentinel for masked
        xs[q] = x;
        lmax = fmaxf(lmax, x);
    }
    float wm = lmax;
    #pragma unroll
    for (int d = 16; d > 0; d >>= 1) wm = fmaxf(wm, __shfl_xor_sync(0xffffffffu, wm, d));
    if (lane == 0) s_red[w] = wm;
    __syncthreads();
    const float m = fmaxf(fmaxf(s_red[0], s_red[1]), fmaxf(s_red[2], s_red[3]));

    float wv[8];
    float lz = 0.0f;
    #pragma unroll
    for (int q = 0; q < 8; ++q) {
        float e = __expf(xs[q] - m);            // masked -> exp(-1e30) = 0
        wv[q] = e;
        lz += e;
    }
    #pragma unroll
    for (int d = 16; d > 0; d >>= 1) lz += __shfl_xor_sync(0xffffffffu, lz, d);
    if (lane == 0) s_red[4 + w] = lz;
    __syncthreads();
    const float Zi = 1.0f / (s_red[4] + s_red[5] + s_red[6] + s_red[7]);

    __half2 hv[4];
    #pragma unroll
    for (int q = 0; q < 4; ++q)
        hv[q] = __floats2half2_rn(wv[2 * q] * Zi, wv[2 * q + 1] * Zi);
    *(int4*)(att + (size_t)bi * NN + tid * 8) = *(const int4*)hv;
}

// ---------------------------------------------------------------------------
// Kernel 3 (r13-validated, unchanged): out = elu(att @ Wh). 128x256 tile per
// CTA, 512 threads, warp tile 32x64, 3-stage cp.async, one sync per chunk.
// ---------------------------------------------------------------------------
#define BPADK 72
#define V4_A_STAGE (128 * BPADK * 2)            // 18432
#define V4_B_STAGE (64 * 264 * 2)               // 33792
#define V4_OFF_B   (3 * V4_A_STAGE)             // 55296
#define V4_SMEM    (V4_OFF_B + 3 * V4_B_STAGE)  // 156672

__global__ __launch_bounds__(512) void bmm_kernel(
    const __half* __restrict__ att, const __half* __restrict__ Wh,
    float* __restrict__ out)
{
    extern __shared__ char bsm[];
    const uint32_t aBase = smem_u32(bsm);
    const uint32_t bBase = aBase + V4_OFF_B;

    const int tid = threadIdx.x, lane = tid & 31, wid = tid >> 5;
    const int warpRow = wid >> 2, warpCol = wid & 3;
    const int b  = blockIdx.x >> 3;
    const int rt = (blockIdx.x & 7) * 128;
    const __half* attB = att + ((size_t)b * NN + rt) * NN;
    const __half* WhB  = Wh + (size_t)b * NN * HH;

    float acc[2][8][4];
    #pragma unroll
    for (int mt = 0; mt < 2; ++mt)
        #pragma unroll
        for (int nt = 0; nt < 8; ++nt)
            #pragma unroll
            for (int e = 0; e < 4; ++e) acc[mt][nt][e] = 0.0f;

    auto load_stage = [&](int kc, int s) {
        const int k0 = kc * 64;
        uint32_t aS = aBase + (uint32_t)s * V4_A_STAGE;
        uint32_t bS = bBase + (uint32_t)s * V4_B_STAGE;
        #pragma unroll
        for (int it = 0; it < 2; ++it) {
            int f = tid + it * 512;                 // 0..1023: 128 rows x 8 segs
            int r = f >> 3, c = (f & 7) * 8;
            CP16(aS + (uint32_t)(r * BPADK + c) * 2,
                 attB + (size_t)r * NN + k0 + c);
        }
        #pragma unroll
        for (int it = 0; it < 4; ++it) {
            int f = tid + it * 512;                 // 0..2047: 64 rows x 32 segs
            int r = f >> 5, c = (f & 31) * 8;
            CP16(bS + (uint32_t)(r * 264 + c) * 2,
                 WhB + (size_t)(k0 + r) * HH + c);
        }
        CP_COMMIT();
    };

    load_stage(0, 0);
    load_stage(1, 1);

    int sIdx = 0;
    for (int kc = 0; kc < 16; ++kc) {
        if (kc == 15) {
            asm volatile("cp.async.wait_group 0;" ::: "memory");
        } else {
            asm volatile("cp.async.wait_group 1;" ::: "memory");
        }
        __syncthreads();   // chunk kc ready; everyone done consuming kc-1

        if (kc + 2 < 16) {
            int s2 = sIdx + 2; if (s2 >= 3) s2 -= 3;
            load_stage(kc + 2, s2);
        }

        const uint32_t aS = aBase + (uint32_t)sIdx * V4_A_STAGE;
        const uint32_t bS = bBase + (uint32_t)sIdx * V4_B_STAGE;
        #pragma unroll
        for (int ks = 0; ks < 4; ++ks) {
            const int kk = ks * 16;
            uint32_t a[2][4];
            #pragma unroll
            for (int mt = 0; mt < 2; ++mt) {
                int row = warpRow * 32 + mt * 16 + (lane & 15);
                int kcol = kk + (lane >> 4) * 8;
                LDSM_X4(a[mt][0], a[mt][1], a[mt][2], a[mt][3],
                        aS + (uint32_t)(row * BPADK + kcol) * 2);
            }
            #pragma unroll
            for (int p = 0; p < 4; ++p) {
                int n = warpCol * 64 + p * 16;
                int krow = kk + (lane & 15);
                int col = n + ((lane >> 4) << 3);
                uint32_t bfr[4];
                LDSM_X4_T(bfr[0], bfr[1], bfr[2], bfr[3],
                          bS + (uint32_t)(krow * 264 + col) * 2);
                #pragma unroll
                for (int mt = 0; mt < 2; ++mt) {
                    MMA_F16(acc[mt][2 * p],     a[mt], bfr[0], bfr[1]);
                    MMA_F16(acc[mt][2 * p + 1], a[mt], bfr[2], bfr[3]);
                }
            }
        }

        ++sIdx; if (sIdx == 3) sIdx = 0;
    }

    // ---- epilogue: elu + fp32 store ----
    const int g = lane >> 2, qc = (lane & 3) * 2;
    #pragma unroll
    for (int mt = 0; mt < 2; ++mt) {
        int lr0 = warpRow * 32 + mt * 16 + g;
        int lr1 = lr0 + 8;
        size_t o0 = ((size_t)b * NN + rt + lr0) * HH;
        size_t o1 = ((size_t)b * NN + rt + lr1) * HH;
        #pragma unroll
        for (int nt = 0; nt < 8; ++nt) {
            int col = warpCol * 64 + nt * 8 + qc;
            float c0 = acc[mt][nt][0], c1 = acc[mt][nt][1];
            float c2 = acc[mt][nt][2], c3 = acc[mt][nt][3];
            float2 r0, r1;
            r0.x = (c0 > 0.0f) ? c0 : expm1f(c0);
            r0.y = (c1 > 0.0f) ? c1 : expm1f(c1);
            r1.x = (c2 > 0.0f) ? c2 : expm1f(c2);
            r1.y = (c3 > 0.0f) ? c3 : expm1f(c3);
            *(float2*)(out + o0 + col) = r0;
            *(float2*)(out + o1 + col) = r1;
        }
    }
}

// ---------------------------------------------------------------------------
extern "C" void kernel_launch(void* const* d_in, const int* in_sizes, int n_in,
                              void* d_out, int out_size)
{
    const float* inp = (const float*)d_in[0];   // [B,N,H]
    const float* A   = (const float*)d_in[1];   // [B,N,N]
    const int*   l   = (const int*)  d_in[2];   // [B,2]
    const float* Wi  = (const float*)d_in[3];   // [H,H]
    const float* Wc  = (const float*)d_in[4];   // [H,H]
    const float* a   = (const float*)d_in[5];   // [2H,1]
    float* out = (float*)d_out;

    __half *WhH, *att;
    cudaGetSymbolAddress((void**)&WhH, g_WhH);
    cudaGetSymbolAddress((void**)&att, g_att);

    cudaFuncSetAttribute(gemm_kernel, cudaFuncAttributeMaxDynamicSharedMemorySize, SMEM_TOT);
    cudaFuncSetAttribute(bmm_kernel, cudaFuncAttributeMaxDynamicSharedMemorySize, V4_SMEM);

    wsplit_kernel<<<2 * HH * HH / 256, 256>>>(Wi, Wc);
    gemm_kernel<<<BB * NN / 128, 512, SMEM_TOT>>>(inp, l, a);
    score_kernel<<<BB * NN, 128>>>(A, att);
    bmm_kernel<<<BB * NN / 128, 512, V4_SMEM>>>(att, WhH, out);
}